// round 3
// baseline (speedup 1.0000x reference)
#include <cuda_runtime.h>
#include <math.h>

#define Nn 64
#define Tt 512
#define Dd 1024
#define Hh 1024
#define G4 4096   // 4*Hh

// packed fp32x2 FMA (Blackwell FFMA2 — PTX-only path)
#define FMA2(d, a, b) asm("fma.rn.f32x2 %0, %1, %2, %0;" : "+l"(d) : "l"(a), "l"(b))

union F2U { unsigned long long u; float2 f; };

// Scratch (device globals: allocation-free rule)
__device__ float g_xw[(size_t)Nn * Tt * G4];  // [N*T, 4H] input projection
__device__ float g_c[Nn * Hh];                // cell state

// ---------------------------------------------------------------------------
__global__ void zero_c_kernel() {
    int i = blockIdx.x * blockDim.x + threadIdx.x;
    if (i < Nn * Hh) g_c[i] = 0.0f;
}

// ---------------------------------------------------------------------------
// xW = x[N*T, D] @ Wx[D, 4H] + b   -> g_xw
// 128x128x8 SGEMM, 256 threads, 8x8 microtile, packed f32x2 FMAs.
// A rows stored DUPLICATED in smem so the broadcast operand is loadable as
// packed pairs; B col-pairs pack naturally from LDS.128.
// ---------------------------------------------------------------------------
__global__ void __launch_bounds__(256) sgemm_xw(const float* __restrict__ A,
                                                const float* __restrict__ B,
                                                const float* __restrict__ bias) {
    __shared__ float Asd[8][256];   // Asd[k][2m..2m+1] = A[m][k] (dup, transposed)
    __shared__ float Bs[8][128];    // Bs[k][n]

    int tid = threadIdx.x;
    int bx = blockIdx.x;   // column tile (0..31)
    int by = blockIdx.y;   // row tile    (0..255)

    int arow = tid >> 1;            // 0..127
    int acol = (tid & 1) * 4;       // 0 or 4
    int brow = tid >> 5;            // 0..7
    int bcol = (tid & 31) * 4;      // 0..124

    const float* Ap = A + (size_t)(by * 128 + arow) * Dd + acol;
    const float* Bp = B + (size_t)brow * G4 + bx * 128 + bcol;

    int tx = tid & 15;   // 8 output cols each (4 packed pairs)
    int ty = tid >> 4;   // 8 output rows each

    unsigned long long acc[8][4];
#pragma unroll
    for (int i = 0; i < 8; i++)
#pragma unroll
        for (int j = 0; j < 4; j++) acc[i][j] = 0ull;

    float4 a4 = *(const float4*)Ap;
    float4 b4 = *(const float4*)Bp;

    for (int k0 = 0; k0 < Dd; k0 += 8) {
        // stage current tile
        Asd[acol + 0][arow * 2] = a4.x; Asd[acol + 0][arow * 2 + 1] = a4.x;
        Asd[acol + 1][arow * 2] = a4.y; Asd[acol + 1][arow * 2 + 1] = a4.y;
        Asd[acol + 2][arow * 2] = a4.z; Asd[acol + 2][arow * 2 + 1] = a4.z;
        Asd[acol + 3][arow * 2] = a4.w; Asd[acol + 3][arow * 2 + 1] = a4.w;
        *(float4*)&Bs[brow][bcol] = b4;
        __syncthreads();

        // prefetch next tile while computing this one
        if (k0 + 8 < Dd) {
            Ap += 8;
            Bp += (size_t)8 * G4;
            a4 = *(const float4*)Ap;
            b4 = *(const float4*)Bp;
        }

#pragma unroll
        for (int kk = 0; kk < 8; kk++) {
            ulonglong2 aa0 = *(const ulonglong2*)&Asd[kk][ty * 16 + 0];   // rows 0,1 (dup)
            ulonglong2 aa1 = *(const ulonglong2*)&Asd[kk][ty * 16 + 4];   // rows 2,3
            ulonglong2 aa2 = *(const ulonglong2*)&Asd[kk][ty * 16 + 8];   // rows 4,5
            ulonglong2 aa3 = *(const ulonglong2*)&Asd[kk][ty * 16 + 12];  // rows 6,7
            ulonglong2 bb0 = *(const ulonglong2*)&Bs[kk][tx * 8];         // col pairs 0,1
            ulonglong2 bb1 = *(const ulonglong2*)&Bs[kk][tx * 8 + 4];     // col pairs 2,3

            FMA2(acc[0][0], aa0.x, bb0.x); FMA2(acc[0][1], aa0.x, bb0.y);
            FMA2(acc[0][2], aa0.x, bb1.x); FMA2(acc[0][3], aa0.x, bb1.y);
            FMA2(acc[1][0], aa0.y, bb0.x); FMA2(acc[1][1], aa0.y, bb0.y);
            FMA2(acc[1][2], aa0.y, bb1.x); FMA2(acc[1][3], aa0.y, bb1.y);
            FMA2(acc[2][0], aa1.x, bb0.x); FMA2(acc[2][1], aa1.x, bb0.y);
            FMA2(acc[2][2], aa1.x, bb1.x); FMA2(acc[2][3], aa1.x, bb1.y);
            FMA2(acc[3][0], aa1.y, bb0.x); FMA2(acc[3][1], aa1.y, bb0.y);
            FMA2(acc[3][2], aa1.y, bb1.x); FMA2(acc[3][3], aa1.y, bb1.y);
            FMA2(acc[4][0], aa2.x, bb0.x); FMA2(acc[4][1], aa2.x, bb0.y);
            FMA2(acc[4][2], aa2.x, bb1.x); FMA2(acc[4][3], aa2.x, bb1.y);
            FMA2(acc[5][0], aa2.y, bb0.x); FMA2(acc[5][1], aa2.y, bb0.y);
            FMA2(acc[5][2], aa2.y, bb1.x); FMA2(acc[5][3], aa2.y, bb1.y);
            FMA2(acc[6][0], aa3.x, bb0.x); FMA2(acc[6][1], aa3.x, bb0.y);
            FMA2(acc[6][2], aa3.x, bb1.x); FMA2(acc[6][3], aa3.x, bb1.y);
            FMA2(acc[7][0], aa3.y, bb0.x); FMA2(acc[7][1], aa3.y, bb0.y);
            FMA2(acc[7][2], aa3.y, bb1.x); FMA2(acc[7][3], aa3.y, bb1.y);
        }
        __syncthreads();
    }

    float bv[8];
    const float* bp = bias + bx * 128 + tx * 8;
#pragma unroll
    for (int j = 0; j < 8; j++) bv[j] = bp[j];

#pragma unroll
    for (int i = 0; i < 8; i++) {
        size_t row = (size_t)(by * 128 + ty * 8 + i);
        float* Cp = g_xw + row * G4 + bx * 128 + tx * 8;
#pragma unroll
        for (int jp = 0; jp < 4; jp++) {
            F2U u; u.u = acc[i][jp];
            Cp[2 * jp + 0] = u.f.x + bv[2 * jp + 0];
            Cp[2 * jp + 1] = u.f.y + bv[2 * jp + 1];
        }
    }
}

// ---------------------------------------------------------------------------
// One LSTM timestep, fully fused.
// Block = 8 h-indices (64x32 a-tile: 4 gates x 8 cols). 256 threads.
// Double-buffered k-tiles of 32, transposed h tile (packed row-pairs),
// duplicated Wh tile (packed broadcast), f32x2 FMAs.
// ---------------------------------------------------------------------------
__global__ void __launch_bounds__(256) lstm_step_kernel(
    const float* __restrict__ hprev, int hstride,
    const float* __restrict__ Wh,
    float* __restrict__ out, int t) {

    __shared__ float Hs[2][32][64];   // Hs[b][k][n]  (transposed)
    __shared__ float Wd[2][32][72];   // Wd[b][k][2c..2c+1] = Wh[k][c] (dup)
    __shared__ float At[64][32];      // a tile for gate epilogue

    int tid = threadIdx.x;
    int hb = blockIdx.x * 8;          // base h-index

    int tx = tid & 15;                // cols {2tx, 2tx+1}
    int ty = tid >> 4;                // rows {4ty..4ty+3}

    // fill mappings
    int hn = tid & 63;                // h row
    int hk4 = (tid >> 6) * 4;         // k offsets {0,4,8,12} (+16 for 2nd half)
    int wk = tid >> 3;                // 0..31 k row
    int wg = (tid >> 1) & 3;          // gate
    int wjh = tid & 1;                // half of 8 cols
    int wc0 = wg * 8 + wjh * 4;       // base a-col (0..31)

    const float* hp = hprev + (size_t)hn * hstride + hk4;
    const float* wp = Wh + (size_t)wk * G4 + hb + wg * 1024 + wjh * 4;

    float4 hA = *(const float4*)(hp);
    float4 hB = *(const float4*)(hp + 16);
    float4 wv = *(const float4*)(wp);

    unsigned long long acc[2][2] = {{0ull, 0ull}, {0ull, 0ull}};

    // stage tile 0
    Hs[0][hk4 + 0][hn] = hA.x;  Hs[0][hk4 + 1][hn] = hA.y;
    Hs[0][hk4 + 2][hn] = hA.z;  Hs[0][hk4 + 3][hn] = hA.w;
    Hs[0][hk4 + 16][hn] = hB.x; Hs[0][hk4 + 17][hn] = hB.y;
    Hs[0][hk4 + 18][hn] = hB.z; Hs[0][hk4 + 19][hn] = hB.w;
    {
        float* wr = &Wd[0][wk][wc0 * 2];
        wr[0] = wv.x; wr[1] = wv.x; wr[2] = wv.y; wr[3] = wv.y;
        wr[4] = wv.z; wr[5] = wv.z; wr[6] = wv.w; wr[7] = wv.w;
    }
    __syncthreads();

    int p = 0;
    for (int tile = 0; tile < 32; tile++) {
        if (tile < 31) {                      // prefetch next tile into regs
            const float* hp2 = hp + (tile + 1) * 32;
            hA = *(const float4*)(hp2);
            hB = *(const float4*)(hp2 + 16);
            wv = *(const float4*)(wp + (size_t)(tile + 1) * 32 * G4);
        }
#pragma unroll
        for (int kk = 0; kk < 32; kk++) {
            ulonglong2 h2 = *(const ulonglong2*)&Hs[p][kk][ty * 4];  // row pairs (0,1),(2,3)
            ulonglong2 w2 = *(const ulonglong2*)&Wd[p][kk][tx * 4];  // (w0,w0),(w1,w1)
            FMA2(acc[0][0], h2.x, w2.x);
            FMA2(acc[0][1], h2.x, w2.y);
            FMA2(acc[1][0], h2.y, w2.x);
            FMA2(acc[1][1], h2.y, w2.y);
        }
        if (tile < 31) {
            int q = p ^ 1;
            Hs[q][hk4 + 0][hn] = hA.x;  Hs[q][hk4 + 1][hn] = hA.y;
            Hs[q][hk4 + 2][hn] = hA.z;  Hs[q][hk4 + 3][hn] = hA.w;
            Hs[q][hk4 + 16][hn] = hB.x; Hs[q][hk4 + 17][hn] = hB.y;
            Hs[q][hk4 + 18][hn] = hB.z; Hs[q][hk4 + 19][hn] = hB.w;
            float* wr = &Wd[q][wk][wc0 * 2];
            wr[0] = wv.x; wr[1] = wv.x; wr[2] = wv.y; wr[3] = wv.y;
            wr[4] = wv.z; wr[5] = wv.z; wr[6] = wv.w; wr[7] = wv.w;
            __syncthreads();
            p = q;
        }
    }

    // unpack accumulators to smem a-tile
#pragma unroll
    for (int rp = 0; rp < 2; rp++)
#pragma unroll
        for (int j = 0; j < 2; j++) {
            F2U u; u.u = acc[rp][j];
            At[ty * 4 + 2 * rp + 0][tx * 2 + j] = u.f.x;
            At[ty * 4 + 2 * rp + 1][tx * 2 + j] = u.f.y;
        }
    __syncthreads();

    // gates + state update: 512 items (n, jj), 2 per thread
#pragma unroll
    for (int itx = 0; itx < 2; itx++) {
        int item = tid + itx * 256;
        int n  = item >> 3;
        int jj = item & 7;

        const float* xwr = g_xw + ((size_t)(n * Tt + t)) * G4 + hb + jj;
        float a0 = At[n][jj]      + xwr[0];       // i
        float a1 = At[n][8 + jj]  + xwr[1024];    // f
        float a2 = At[n][16 + jj] + xwr[2048];    // o
        float a3 = At[n][24 + jj] + xwr[3072];    // g

        float iv = 1.0f / (1.0f + expf(-a0));
        float fv = 1.0f / (1.0f + expf(-a1));
        float ov = 1.0f / (1.0f + expf(-a2));
        float gv = tanhf(a3);

        int hcol = hb + jj;
        float cp = g_c[n * Hh + hcol];
        float cn = fv * cp + iv * gv;
        float hv = ov * tanhf(cn);

        g_c[n * Hh + hcol] = cn;
        out[((size_t)n * Tt + t) * Hh + hcol] = hv;
    }
}

// ---------------------------------------------------------------------------
extern "C" void kernel_launch(void* const* d_in, const int* in_sizes, int n_in,
                              void* d_out, int out_size) {
    const float* x  = (const float*)d_in[0];   // [N,T,D]
    const float* h0 = (const float*)d_in[1];   // [N,H]
    const float* Wx = (const float*)d_in[2];   // [D,4H]
    const float* Wh = (const float*)d_in[3];   // [H,4H]
    const float* b  = (const float*)d_in[4];   // [4H]
    float* out = (float*)d_out;                // [N,T,H]

    zero_c_kernel<<<(Nn * Hh + 255) / 256, 256>>>();

    dim3 g1(G4 / 128, (Nn * Tt) / 128);        // (32, 256)
    sgemm_xw<<<g1, 256>>>(x, Wx, b);

    for (int t = 0; t < Tt; t++) {
        const float* hprev = (t == 0) ? h0 : (const float*)(out + (size_t)(t - 1) * Hh);
        int hstride = (t == 0) ? Hh : Tt * Hh;
        lstm_step_kernel<<<128, 256>>>(hprev, hstride, Wh, out, t);
    }
}

// round 5
// speedup vs baseline: 1.5405x; 1.5405x over previous
#include <cuda_runtime.h>
#include <math.h>

#define Nn 64
#define Tt 512
#define Dd 1024
#define Hh 1024
#define G4 4096   // 4*Hh
#define KSPL 4
#define KPER 256  // Hh / KSPL
#define NBLK 128  // persistent grid size (<=148 SMs -> co-resident)

// packed fp32x2 FMA (Blackwell FFMA2 — PTX-only path)
#define FMA2(d, a, b) asm("fma.rn.f32x2 %0, %1, %2, %0;" : "+l"(d) : "l"(a), "l"(b))

union F2U { unsigned long long u; float2 f; };

// Scratch (device globals: allocation-free rule)
__device__ float g_xw[(size_t)Nn * Tt * G4];   // [N*T, 4H] input projection
__device__ float g_c[Nn * Hh];                 // cell state
__device__ float g_p[KSPL][Nn][G4];            // per-K-split partials of h@Wh

// grid barrier state (zero-initialized; gen is monotonic across replays)
__device__ unsigned g_count = 0;
__device__ unsigned g_gen = 0;

__device__ __forceinline__ void grid_barrier() {
    __syncthreads();
    if (threadIdx.x == 0) {
        __threadfence();                         // publish my block's writes
        unsigned gen = atomicAdd(&g_gen, 0u);    // read BEFORE arriving
        if (atomicAdd(&g_count, 1u) == NBLK - 1) {
            atomicExch(&g_count, 0u);
            atomicAdd(&g_gen, 1u);               // release
        } else {
            while (atomicAdd(&g_gen, 0u) == gen) __nanosleep(64);
        }
    }
    __syncthreads();
}

// ---------------------------------------------------------------------------
// xW = x[N*T, D] @ Wx[D, 4H] + b   -> g_xw
// 128x128x8 SGEMM, 256 threads, 8x8 microtile, packed f32x2 FMAs.
// ---------------------------------------------------------------------------
__global__ void __launch_bounds__(256) sgemm_xw(const float* __restrict__ A,
                                                const float* __restrict__ B,
                                                const float* __restrict__ bias) {
    __shared__ float Asd[8][256];   // Asd[k][2m..2m+1] = A[m][k] (dup, transposed)
    __shared__ float Bs[8][128];    // Bs[k][n]

    int tid = threadIdx.x;
    int bx = blockIdx.x;
    int by = blockIdx.y;

    int arow = tid >> 1;
    int acol = (tid & 1) * 4;
    int brow = tid >> 5;
    int bcol = (tid & 31) * 4;

    const float* Ap = A + (size_t)(by * 128 + arow) * Dd + acol;
    const float* Bp = B + (size_t)brow * G4 + bx * 128 + bcol;

    int tx = tid & 15;
    int ty = tid >> 4;

    unsigned long long acc[8][4];
#pragma unroll
    for (int i = 0; i < 8; i++)
#pragma unroll
        for (int j = 0; j < 4; j++) acc[i][j] = 0ull;

    float4 a4 = *(const float4*)Ap;
    float4 b4 = *(const float4*)Bp;

    for (int k0 = 0; k0 < Dd; k0 += 8) {
        Asd[acol + 0][arow * 2] = a4.x; Asd[acol + 0][arow * 2 + 1] = a4.x;
        Asd[acol + 1][arow * 2] = a4.y; Asd[acol + 1][arow * 2 + 1] = a4.y;
        Asd[acol + 2][arow * 2] = a4.z; Asd[acol + 2][arow * 2 + 1] = a4.z;
        Asd[acol + 3][arow * 2] = a4.w; Asd[acol + 3][arow * 2 + 1] = a4.w;
        *(float4*)&Bs[brow][bcol] = b4;
        __syncthreads();

        if (k0 + 8 < Dd) {
            Ap += 8;
            Bp += (size_t)8 * G4;
            a4 = *(const float4*)Ap;
            b4 = *(const float4*)Bp;
        }

#pragma unroll
        for (int kk = 0; kk < 8; kk++) {
            ulonglong2 aa0 = *(const ulonglong2*)&Asd[kk][ty * 16 + 0];
            ulonglong2 aa1 = *(const ulonglong2*)&Asd[kk][ty * 16 + 4];
            ulonglong2 aa2 = *(const ulonglong2*)&Asd[kk][ty * 16 + 8];
            ulonglong2 aa3 = *(const ulonglong2*)&Asd[kk][ty * 16 + 12];
            ulonglong2 bb0 = *(const ulonglong2*)&Bs[kk][tx * 8];
            ulonglong2 bb1 = *(const ulonglong2*)&Bs[kk][tx * 8 + 4];

            FMA2(acc[0][0], aa0.x, bb0.x); FMA2(acc[0][1], aa0.x, bb0.y);
            FMA2(acc[0][2], aa0.x, bb1.x); FMA2(acc[0][3], aa0.x, bb1.y);
            FMA2(acc[1][0], aa0.y, bb0.x); FMA2(acc[1][1], aa0.y, bb0.y);
            FMA2(acc[1][2], aa0.y, bb1.x); FMA2(acc[1][3], aa0.y, bb1.y);
            FMA2(acc[2][0], aa1.x, bb0.x); FMA2(acc[2][1], aa1.x, bb0.y);
            FMA2(acc[2][2], aa1.x, bb1.x); FMA2(acc[2][3], aa1.x, bb1.y);
            FMA2(acc[3][0], aa1.y, bb0.x); FMA2(acc[3][1], aa1.y, bb0.y);
            FMA2(acc[3][2], aa1.y, bb1.x); FMA2(acc[3][3], aa1.y, bb1.y);
            FMA2(acc[4][0], aa2.x, bb0.x); FMA2(acc[4][1], aa2.x, bb0.y);
            FMA2(acc[4][2], aa2.x, bb1.x); FMA2(acc[4][3], aa2.x, bb1.y);
            FMA2(acc[5][0], aa2.y, bb0.x); FMA2(acc[5][1], aa2.y, bb0.y);
            FMA2(acc[5][2], aa2.y, bb1.x); FMA2(acc[5][3], aa2.y, bb1.y);
            FMA2(acc[6][0], aa3.x, bb0.x); FMA2(acc[6][1], aa3.x, bb0.y);
            FMA2(acc[6][2], aa3.x, bb1.x); FMA2(acc[6][3], aa3.x, bb1.y);
            FMA2(acc[7][0], aa3.y, bb0.x); FMA2(acc[7][1], aa3.y, bb0.y);
            FMA2(acc[7][2], aa3.y, bb1.x); FMA2(acc[7][3], aa3.y, bb1.y);
        }
        __syncthreads();
    }

    float bv[8];
    const float* bp = bias + bx * 128 + tx * 8;
#pragma unroll
    for (int j = 0; j < 8; j++) bv[j] = bp[j];

#pragma unroll
    for (int i = 0; i < 8; i++) {
        size_t row = (size_t)(by * 128 + ty * 8 + i);
        float* Cp = g_xw + row * G4 + bx * 128 + tx * 8;
#pragma unroll
        for (int jp = 0; jp < 4; jp++) {
            F2U u; u.u = acc[i][jp];
            Cp[2 * jp + 0] = u.f.x + bv[2 * jp + 0];
            Cp[2 * jp + 1] = u.f.y + bv[2 * jp + 1];
        }
    }
}

// ---------------------------------------------------------------------------
// Persistent LSTM recurrence: one launch, 128 co-resident blocks, t-loop with
// grid barriers. Per step: K-split GEMM phase (block (ntile,ks): 64x128 tile,
// K=256) -> barrier -> epilogue phase (512 (n,hc) items per block) -> barrier.
// ---------------------------------------------------------------------------
__global__ void __launch_bounds__(256) lstm_persist(const float* __restrict__ h0,
                                                    const float* __restrict__ Wh,
                                                    float* __restrict__ out) {
    __shared__ float Hd[2][16][128];   // Hd[b][kk][2m..2m+1] = h[m][kk] (dup)
    __shared__ float Ws[2][16][128];   // Ws[b][kk][c]

    int tid = threadIdx.x;
    int bid = blockIdx.x;
    int ntile = bid & 31;              // 0..31
    int ks = bid >> 5;                 // 0..3
    int c0 = ntile * 128;
    int k0 = ks * KPER;

    int tx = tid & 15;                 // col group
    int ty = tid >> 4;                 // row group (rows 4ty..4ty+3)

    // staging mappings
    int hr = tid >> 2;                 // 0..63 (h row)
    int hk = (tid & 3) * 4;            // 0,4,8,12
    int wr = tid >> 4;                 // 0..15 (k row)
    int wc = (tid & 15) * 8;           // 0..120

    const float* wp0 = Wh + (size_t)(k0 + wr) * G4 + c0 + wc;

    // epilogue mapping: items bid*512 + tid, + 256
    int eidx0 = bid * 512 + tid;

    for (int t = 0; t < Tt; t++) {
        const float* hprev = (t == 0) ? h0 : (out + (size_t)(t - 1) * Hh);
        int hstride = (t == 0) ? Hh : Tt * Hh;

        // ---- GEMM phase ----
        const float* hp = hprev + (size_t)hr * hstride + k0 + hk;
        const float* wp = wp0;

        float4 h4  = *(const float4*)hp;
        float4 wa4 = *(const float4*)wp;
        float4 wb4 = *(const float4*)(wp + 4);

        unsigned long long acc[4][4];
#pragma unroll
        for (int r = 0; r < 4; r++)
#pragma unroll
            for (int j = 0; j < 4; j++) acc[r][j] = 0ull;

        Hd[0][hk + 0][2 * hr] = h4.x; Hd[0][hk + 0][2 * hr + 1] = h4.x;
        Hd[0][hk + 1][2 * hr] = h4.y; Hd[0][hk + 1][2 * hr + 1] = h4.y;
        Hd[0][hk + 2][2 * hr] = h4.z; Hd[0][hk + 2][2 * hr + 1] = h4.z;
        Hd[0][hk + 3][2 * hr] = h4.w; Hd[0][hk + 3][2 * hr + 1] = h4.w;
        *(float4*)&Ws[0][wr][wc] = wa4;
        *(float4*)&Ws[0][wr][wc + 4] = wb4;
        __syncthreads();

        int p = 0;
        for (int tile = 0; tile < 16; tile++) {
            if (tile < 15) {           // prefetch next k-tile
                hp += 16;
                wp += (size_t)16 * G4;
                h4  = *(const float4*)hp;
                wa4 = *(const float4*)wp;
                wb4 = *(const float4*)(wp + 4);
            }
#pragma unroll
            for (int kk = 0; kk < 16; kk++) {
                ulonglong2 ha = *(const ulonglong2*)&Hd[p][kk][ty * 8];
                ulonglong2 hb = *(const ulonglong2*)&Hd[p][kk][ty * 8 + 4];
                ulonglong2 wa = *(const ulonglong2*)&Ws[p][kk][tx * 4];
                ulonglong2 wb = *(const ulonglong2*)&Ws[p][kk][64 + tx * 4];

                FMA2(acc[0][0], ha.x, wa.x); FMA2(acc[0][1], ha.x, wa.y);
                FMA2(acc[0][2], ha.x, wb.x); FMA2(acc[0][3], ha.x, wb.y);
                FMA2(acc[1][0], ha.y, wa.x); FMA2(acc[1][1], ha.y, wa.y);
                FMA2(acc[1][2], ha.y, wb.x); FMA2(acc[1][3], ha.y, wb.y);
                FMA2(acc[2][0], hb.x, wa.x); FMA2(acc[2][1], hb.x, wa.y);
                FMA2(acc[2][2], hb.x, wb.x); FMA2(acc[2][3], hb.x, wb.y);
                FMA2(acc[3][0], hb.y, wa.x); FMA2(acc[3][1], hb.y, wa.y);
                FMA2(acc[3][2], hb.y, wb.x); FMA2(acc[3][3], hb.y, wb.y);
            }
            if (tile < 15) {
                int q = p ^ 1;
                Hd[q][hk + 0][2 * hr] = h4.x; Hd[q][hk + 0][2 * hr + 1] = h4.x;
                Hd[q][hk + 1][2 * hr] = h4.y; Hd[q][hk + 1][2 * hr + 1] = h4.y;
                Hd[q][hk + 2][2 * hr] = h4.z; Hd[q][hk + 2][2 * hr + 1] = h4.z;
                Hd[q][hk + 3][2 * hr] = h4.w; Hd[q][hk + 3][2 * hr + 1] = h4.w;
                *(float4*)&Ws[q][wr][wc] = wa4;
                *(float4*)&Ws[q][wr][wc + 4] = wb4;
                __syncthreads();
                p = q;
            }
        }

        // write partials (block-exclusive region)
#pragma unroll
        for (int r = 0; r < 4; r++) {
            int row = ty * 4 + r;
            F2U u0, u1;
            u0.u = acc[r][0]; u1.u = acc[r][1];
            float4 v0 = make_float4(u0.f.x, u0.f.y, u1.f.x, u1.f.y);
            u0.u = acc[r][2]; u1.u = acc[r][3];
            float4 v1 = make_float4(u0.f.x, u0.f.y, u1.f.x, u1.f.y);
            *(float4*)&g_p[ks][row][c0 + tx * 4] = v0;
            *(float4*)&g_p[ks][row][c0 + 64 + tx * 4] = v1;
        }

        grid_barrier();

        // ---- epilogue phase: 2 items per thread ----
#pragma unroll
        for (int it = 0; it < 2; it++) {
            int idx = eidx0 + it * 256;
            int n = idx >> 10;
            int hc = idx & 1023;

            const float* xw = g_xw + (size_t)(n * Tt + t) * G4 + hc;

            // cross-block data: L2-only loads (L1 is stale across steps)
            float a0 = __ldcg(&g_p[0][n][hc])        + __ldcg(&g_p[1][n][hc])
                     + __ldcg(&g_p[2][n][hc])        + __ldcg(&g_p[3][n][hc])        + xw[0];
            float a1 = __ldcg(&g_p[0][n][1024 + hc]) + __ldcg(&g_p[1][n][1024 + hc])
                     + __ldcg(&g_p[2][n][1024 + hc]) + __ldcg(&g_p[3][n][1024 + hc]) + xw[1024];
            float a2 = __ldcg(&g_p[0][n][2048 + hc]) + __ldcg(&g_p[1][n][2048 + hc])
                     + __ldcg(&g_p[2][n][2048 + hc]) + __ldcg(&g_p[3][n][2048 + hc]) + xw[2048];
            float a3 = __ldcg(&g_p[0][n][3072 + hc]) + __ldcg(&g_p[1][n][3072 + hc])
                     + __ldcg(&g_p[2][n][3072 + hc]) + __ldcg(&g_p[3][n][3072 + hc]) + xw[3072];

            float iv = 1.0f / (1.0f + expf(-a0));
            float fv = 1.0f / (1.0f + expf(-a1));
            float ov = 1.0f / (1.0f + expf(-a2));
            float gv = tanhf(a3);

            float cp = (t == 0) ? 0.0f : g_c[idx];
            float cn = fv * cp + iv * gv;
            float hv = ov * tanhf(cn);

            g_c[idx] = cn;
            out[((size_t)n * Tt + t) * Hh + hc] = hv;
        }

        grid_barrier();
    }
}

// ---------------------------------------------------------------------------
extern "C" void kernel_launch(void* const* d_in, const int* in_sizes, int n_in,
                              void* d_out, int out_size) {
    const float* x  = (const float*)d_in[0];   // [N,T,D]
    const float* h0 = (const float*)d_in[1];   // [N,H]
    const float* Wx = (const float*)d_in[2];   // [D,4H]
    const float* Wh = (const float*)d_in[3];   // [H,4H]
    const float* b  = (const float*)d_in[4];   // [4H]
    float* out = (float*)d_out;                // [N,T,H]

    dim3 g1(G4 / 128, (Nn * Tt) / 128);        // (32, 256)
    sgemm_xw<<<g1, 256>>>(x, Wx, b);

    lstm_persist<<<NBLK, 256>>>(h0, Wh, out);
}